// round 13
// baseline (speedup 1.0000x reference)
#include <cuda_runtime.h>
#include <math.h>

#define Bsz 1024
#define Ssz 350
#define Vsz 41
#define BT 4
#define NCTA 256
#define NTHR 256

typedef unsigned long long u64;

// ---------------- persistent device scratch ----------------
__device__ float4 g_wA[49152];     // Whh0: [kc][gate][256] -> W[g*256+t][4kc..4kc+3]
__device__ float4 g_wB1[24576];    // Wih1: [kc][gate][128]
__device__ float4 g_wB2[12288];    // Whh1: [kc][gate][128]
__device__ float4 g_wC1[3072];     // Wih2: [kc][gate][32]
__device__ float4 g_wC2[768];      // Whh2: [kc][gate][32]
__device__ float  g_WprojT[1312];  // [k][j]
__device__ float  g_G0[41 * 768];  // [v][col] = bih0 + Wih0 @ emb[v]
__device__ float  g_Hinit[Bsz * 416];

// ---------------- f32x2 helpers ----------------
__device__ __forceinline__ u64 fma2(u64 a, u64 b, u64 c) {
    u64 d; asm("fma.rn.f32x2 %0,%1,%2,%3;" : "=l"(d) : "l"(a), "l"(b), "l"(c)); return d;
}
__device__ __forceinline__ u64 pk2(float x, float y) {
    u64 d; asm("mov.b64 %0,{%1,%2};" : "=l"(d) : "f"(x), "f"(y)); return d;
}
__device__ __forceinline__ void up2(u64 a, float& x, float& y) {
    asm("mov.b64 {%0,%1}, %2;" : "=f"(x), "=f"(y) : "l"(a));
}
__device__ __forceinline__ float sigf(float x) {
    return __fdividef(1.0f, 1.0f + __expf(-x));
}
__device__ __forceinline__ float tanh_(float x) {
    float ax = fabsf(x);
    float e = __expf(-2.0f * ax);
    float t = __fdividef(1.0f - e, 1.0f + e);
    return copysignf(t, x);
}

// ---------------- fused prep kernel (identical to R12) ----------------
__global__ void k_prep(const float* __restrict__ latent, const float* __restrict__ W_emb,
                       const float* __restrict__ b_emb, const float* __restrict__ W_init,
                       const float* __restrict__ b_init, const float* __restrict__ Wih0,
                       const float* __restrict__ bih0, const float* __restrict__ Whh0,
                       const float* __restrict__ Wih1, const float* __restrict__ Whh1,
                       const float* __restrict__ Wih2, const float* __restrict__ Whh2,
                       const float* __restrict__ W_proj) {
    const int b = blockIdx.x, tid = threadIdx.x;
    if (b < 128) {
        __shared__ float lat[8 * 512];
        const int b0 = b * 8;
        for (int i = tid; i < 8 * 512; i += NTHR) lat[i] = latent[(size_t)b0 * 512 + i];
        __syncthreads();
        for (int c = tid; c < 416; c += NTHR) {
            float acc[8];
            float bi = b_init[c];
#pragma unroll
            for (int r = 0; r < 8; r++) acc[r] = bi;
            const float* w = W_init + (size_t)c * 512;
            for (int k = 0; k < 512; k += 4) {
                float4 wv = *(const float4*)(w + k);
#pragma unroll
                for (int r = 0; r < 8; r++) {
                    acc[r] += wv.x * lat[r * 512 + k];
                    acc[r] += wv.y * lat[r * 512 + k + 1];
                    acc[r] += wv.z * lat[r * 512 + k + 2];
                    acc[r] += wv.w * lat[r * 512 + k + 3];
                }
            }
#pragma unroll
            for (int r = 0; r < 8; r++) g_Hinit[(size_t)(b0 + r) * 416 + c] = acc[r];
        }
    } else if (b < 169) {
        const int v = b - 128;
        __shared__ float emb[512];
        for (int k = tid; k < 512; k += NTHR) emb[k] = W_emb[k * Vsz + v] + b_emb[k];
        __syncthreads();
        for (int j = tid; j < 768; j += NTHR) {
            float acc = bih0[j];
            const float* w = Wih0 + (size_t)j * 512;
            for (int k = 0; k < 512; k += 4) {
                float4 wv = *(const float4*)(w + k);
                acc += wv.x * emb[k] + wv.y * emb[k + 1] + wv.z * emb[k + 2] + wv.w * emb[k + 3];
            }
            g_G0[v * 768 + j] = acc;
        }
    } else {
        const int TOTAL = 90184;
        for (int i = (b - 169) * NTHR + tid; i < TOTAL; i += 87 * NTHR) {
            if (i < 49152) {
                int kc = i / 768, rem = i % 768;
                g_wA[i] = *(const float4*)&Whh0[(size_t)rem * 256 + 4 * kc];
            } else if (i < 73728) {
                int t = i - 49152;
                int kc = t / 384, row = t % 384;
                g_wB1[t] = *(const float4*)&Wih1[(size_t)row * 256 + 4 * kc];
            } else if (i < 86016) {
                int t = i - 73728;
                int kc = t / 384, row = t % 384;
                g_wB2[t] = *(const float4*)&Whh1[(size_t)row * 128 + 4 * kc];
            } else if (i < 89088) {
                int t = i - 86016;
                int kc = t / 96, row = t % 96;
                g_wC1[t] = *(const float4*)&Wih2[(size_t)row * 128 + 4 * kc];
            } else if (i < 89856) {
                int t = i - 89088;
                int kc = t / 96, row = t % 96;
                g_wC2[t] = *(const float4*)&Whh2[(size_t)row * 32 + 4 * kc];
            } else {
                int t2 = i - 89856;
#pragma unroll
                for (int c = 0; c < 4; c++) {
                    int e = t2 * 4 + c;
                    if (e < 1312) {
                        int k = e / Vsz, j = e - k * Vsz;
                        g_WprojT[e] = W_proj[j * 32 + k];
                    }
                }
            }
        }
    }
}

// ---------------- main persistent GRU kernel (column-owner, BT=4, 2 CTA/SM) ----------------
__global__ __launch_bounds__(NTHR, 2)
void k_main(const int* __restrict__ tokens,
            const float* __restrict__ bhh0,
            const float* __restrict__ bih1, const float* __restrict__ bhh1,
            const float* __restrict__ bih2, const float* __restrict__ bhh2,
            const float* __restrict__ b_proj,
            float* __restrict__ out, float* __restrict__ pred) {
    // h layouts: [k][rp] row-pairs (2 rps for BT=4)
    __shared__ __align__(16) u64 hrp0[256 * 2];
    __shared__ __align__(16) u64 hrp1[128 * 2];
    __shared__ __align__(16) u64 hrp2[32 * 2];
    __shared__ float lg[BT][44];
    __shared__ int toksAll[Ssz * BT];

    const int tid = threadIdx.x;
    const int b0 = blockIdx.x * BT;
    const int jj = tid & 127;          // phase B column
    const int rh = tid >> 7;           // phase B rp index (0/1)
    const int jc = tid & 31;           // phase C column
    const int qC = tid >> 5;           // phase C rp (valid when tid<64)

    // tokens preload (SOS at step 0)
    for (int i = tid; i < Ssz * BT; i += NTHR) {
        int stt = i >> 2, row = i & 3;
        toksAll[i] = (stt == 0) ? 1 : tokens[(size_t)(b0 + row) * Ssz + stt];
    }

    // initial state -> row-pair smem ([k][rp] float view = [k*4 + row])
    for (int idx = tid; idx < BT * 416; idx += NTHR) {
        int row = idx / 416, c = idx - row * 416;
        float v = g_Hinit[(size_t)(b0 + row) * 416 + c];
        if (c < 256)      ((float*)hrp0)[c * 4 + row] = v;
        else if (c < 384) ((float*)hrp1)[(c - 256) * 4 + row] = v;
        else              ((float*)hrp2)[(c - 384) * 4 + row] = v;
    }

    // biases
    const float bR0 = bhh0[tid], bZ0 = bhh0[256 + tid], bN0 = bhh0[512 + tid];
    const u64 bN0d = pk2(bN0, bN0);
    const u64 bBr = pk2(bih1[jj] + bhh1[jj], bih1[jj] + bhh1[jj]);
    const u64 bBz = pk2(bih1[128 + jj] + bhh1[128 + jj], bih1[128 + jj] + bhh1[128 + jj]);
    const u64 bBi = pk2(bih1[256 + jj], bih1[256 + jj]);
    const u64 bBh = pk2(bhh1[256 + jj], bhh1[256 + jj]);
    const u64 bCr = pk2(bih2[jc] + bhh2[jc], bih2[jc] + bhh2[jc]);
    const u64 bCz = pk2(bih2[32 + jc] + bhh2[32 + jc], bih2[32 + jc] + bhh2[32 + jc]);
    const u64 bCi = pk2(bih2[64 + jc], bih2[64 + jc]);
    const u64 bCh = pk2(bhh2[64 + jc], bhh2[64 + jc]);

    const float4* wAp = g_wA + tid;
    const float4* wB1p = g_wB1 + jj;
    const float4* wB2p = g_wB2 + jj;
    const float4* wC1p = g_wC1 + jc;
    const float4* wC2p = g_wC2 + jc;

    __syncthreads();

    for (int st = 0; st < Ssz; st++) {
        const int* tokrow = toksAll + st * BT;

        // ======== Phase A: layer 0 — thread owns all gates of col tid, 4 rows ========
        {
            u64 aR[2], aZ[2], aN[2];
#pragma unroll
            for (int rp = 0; rp < 2; rp++) {
                const float* ge = g_G0 + (size_t)tokrow[2 * rp] * 768;
                const float* go = g_G0 + (size_t)tokrow[2 * rp + 1] * 768;
                aR[rp] = pk2(ge[tid] + bR0, go[tid] + bR0);
                aZ[rp] = pk2(ge[256 + tid] + bZ0, go[256 + tid] + bZ0);
                aN[rp] = bN0d;
            }
            for (int kc = 0; kc < 64; kc++) {
                float4 wr = wAp[kc * 768];
                float4 wz = wAp[kc * 768 + 256];
                float4 wn = wAp[kc * 768 + 512];
                const float wrr[4] = {wr.x, wr.y, wr.z, wr.w};
                const float wzz[4] = {wz.x, wz.y, wz.z, wz.w};
                const float wnn[4] = {wn.x, wn.y, wn.z, wn.w};
#pragma unroll
                for (int c = 0; c < 4; c++) {
                    int k = 4 * kc + c;
                    ulonglong2 hA = *(const ulonglong2*)&hrp0[k * 2];
                    u64 wrd = pk2(wrr[c], wrr[c]);
                    u64 wzd = pk2(wzz[c], wzz[c]);
                    u64 wnd = pk2(wnn[c], wnn[c]);
                    aR[0] = fma2(wrd, hA.x, aR[0]); aR[1] = fma2(wrd, hA.y, aR[1]);
                    aZ[0] = fma2(wzd, hA.x, aZ[0]); aZ[1] = fma2(wzd, hA.y, aZ[1]);
                    aN[0] = fma2(wnd, hA.x, aN[0]); aN[1] = fma2(wnd, hA.y, aN[1]);
                }
            }
            __syncthreads();
#pragma unroll
            for (int rp = 0; rp < 2; rp++) {
                float r0e, r1e, z0e, z1e, n0e, n1e, h0e, h1e;
                up2(aR[rp], r0e, r1e); up2(aZ[rp], z0e, z1e); up2(aN[rp], n0e, n1e);
                float gi0 = g_G0[(size_t)tokrow[2 * rp] * 768 + 512 + tid];
                float gi1 = g_G0[(size_t)tokrow[2 * rp + 1] * 768 + 512 + tid];
                up2(hrp0[tid * 2 + rp], h0e, h1e);
                float rg0 = sigf(r0e), rg1 = sigf(r1e);
                float zg0 = sigf(z0e), zg1 = sigf(z1e);
                float ng0 = tanh_(gi0 + rg0 * n0e), ng1 = tanh_(gi1 + rg1 * n1e);
                float v0 = (1.0f - zg0) * ng0 + zg0 * h0e;
                float v1 = (1.0f - zg1) * ng1 + zg1 * h1e;
                hrp0[tid * 2 + rp] = pk2(v0, v1);
            }
            __syncthreads();
        }

        // ======== Phase B: layer 1 — thread (jj, rh): all gates of col jj, 2 rows ========
        {
            u64 rB = bBr, zB = bBz, iB = bBi, hB = bBh;
            for (int kc = 0; kc < 64; kc++) {
                float4 wr = wB1p[kc * 384];
                float4 wz = wB1p[kc * 384 + 128];
                float4 wn = wB1p[kc * 384 + 256];
                const float wrr[4] = {wr.x, wr.y, wr.z, wr.w};
                const float wzz[4] = {wz.x, wz.y, wz.z, wz.w};
                const float wnn[4] = {wn.x, wn.y, wn.z, wn.w};
#pragma unroll
                for (int c = 0; c < 4; c++) {
                    int k = 4 * kc + c;
                    u64 h = hrp0[k * 2 + rh];
                    rB = fma2(pk2(wrr[c], wrr[c]), h, rB);
                    zB = fma2(pk2(wzz[c], wzz[c]), h, zB);
                    iB = fma2(pk2(wnn[c], wnn[c]), h, iB);
                }
            }
            for (int kc = 0; kc < 32; kc++) {
                float4 wr = wB2p[kc * 384];
                float4 wz = wB2p[kc * 384 + 128];
                float4 wn = wB2p[kc * 384 + 256];
                const float wrr[4] = {wr.x, wr.y, wr.z, wr.w};
                const float wzz[4] = {wz.x, wz.y, wz.z, wz.w};
                const float wnn[4] = {wn.x, wn.y, wn.z, wn.w};
#pragma unroll
                for (int c = 0; c < 4; c++) {
                    int k = 4 * kc + c;
                    u64 h = hrp1[k * 2 + rh];
                    rB = fma2(pk2(wrr[c], wrr[c]), h, rB);
                    zB = fma2(pk2(wzz[c], wzz[c]), h, zB);
                    hB = fma2(pk2(wnn[c], wnn[c]), h, hB);
                }
            }
            __syncthreads();
            {
                float r0e, r1e, z0e, z1e, i0e, i1e, n0e, n1e, h0e, h1e;
                up2(rB, r0e, r1e); up2(zB, z0e, z1e);
                up2(iB, i0e, i1e); up2(hB, n0e, n1e);
                up2(hrp1[jj * 2 + rh], h0e, h1e);
                float rg0 = sigf(r0e), rg1 = sigf(r1e);
                float zg0 = sigf(z0e), zg1 = sigf(z1e);
                float ng0 = tanh_(i0e + rg0 * n0e), ng1 = tanh_(i1e + rg1 * n1e);
                float v0 = (1.0f - zg0) * ng0 + zg0 * h0e;
                float v1 = (1.0f - zg1) * ng1 + zg1 * h1e;
                hrp1[jj * 2 + rh] = pk2(v0, v1);
            }
            __syncthreads();
        }

        // ======== Phase C: layer 2 — threads 0..63: (jc, qC): all gates, 2 rows ========
        if (tid < 64) {
            u64 rC = bCr, zC = bCz, iC = bCi, hC = bCh;
            for (int kc = 0; kc < 32; kc++) {
                float4 wr = wC1p[kc * 96];
                float4 wz = wC1p[kc * 96 + 32];
                float4 wn = wC1p[kc * 96 + 64];
                const float wrr[4] = {wr.x, wr.y, wr.z, wr.w};
                const float wzz[4] = {wz.x, wz.y, wz.z, wz.w};
                const float wnn[4] = {wn.x, wn.y, wn.z, wn.w};
#pragma unroll
                for (int c = 0; c < 4; c++) {
                    u64 h = hrp1[(4 * kc + c) * 2 + qC];
                    rC = fma2(pk2(wrr[c], wrr[c]), h, rC);
                    zC = fma2(pk2(wzz[c], wzz[c]), h, zC);
                    iC = fma2(pk2(wnn[c], wnn[c]), h, iC);
                }
            }
            for (int kc = 0; kc < 8; kc++) {
                float4 wr = wC2p[kc * 96];
                float4 wz = wC2p[kc * 96 + 32];
                float4 wn = wC2p[kc * 96 + 64];
                const float wrr[4] = {wr.x, wr.y, wr.z, wr.w};
                const float wzz[4] = {wz.x, wz.y, wz.z, wz.w};
                const float wnn[4] = {wn.x, wn.y, wn.z, wn.w};
#pragma unroll
                for (int c = 0; c < 4; c++) {
                    u64 h = hrp2[(4 * kc + c) * 2 + qC];
                    rC = fma2(pk2(wrr[c], wrr[c]), h, rC);
                    zC = fma2(pk2(wzz[c], wzz[c]), h, zC);
                    hC = fma2(pk2(wnn[c], wnn[c]), h, hC);
                }
            }
            __syncthreads();
            {
                float r0e, r1e, z0e, z1e, i0e, i1e, n0e, n1e, h0e, h1e;
                up2(rC, r0e, r1e); up2(zC, z0e, z1e);
                up2(iC, i0e, i1e); up2(hC, n0e, n1e);
                up2(hrp2[jc * 2 + qC], h0e, h1e);
                float rg0 = sigf(r0e), rg1 = sigf(r1e);
                float zg0 = sigf(z0e), zg1 = sigf(z1e);
                float ng0 = tanh_(i0e + rg0 * n0e), ng1 = tanh_(i1e + rg1 * n1e);
                float v0 = (1.0f - zg0) * ng0 + zg0 * h0e;
                float v1 = (1.0f - zg1) * ng1 + zg1 * h1e;
                hrp2[jc * 2 + qC] = pk2(v0, v1);
            }
        } else {
            __syncthreads();
        }
        __syncthreads();

        // ======== Phase D: projection + argmax ========
        {
            const float* h2f = (const float*)hrp2;   // [k*4 + row]
            if (tid < BT * Vsz) {
                int row = tid / Vsz, j = tid - row * Vsz;
                float acc = b_proj[j];
#pragma unroll
                for (int k = 0; k < 32; k++)
                    acc += g_WprojT[k * Vsz + j] * h2f[k * 4 + row];
                out[((size_t)(b0 + row) * Ssz + st) * Vsz + j] = acc;
                lg[row][j] = acc;
            }
        }
        __syncthreads();
        if (tid < BT && pred) {
            float best = lg[tid][0];
            int bi = 0;
#pragma unroll 1
            for (int j = 1; j < Vsz; j++) {
                float v = lg[tid][j];
                if (v > best) { best = v; bi = j; }
            }
            pred[(size_t)(b0 + tid) * Ssz + st] = (float)bi;
        }
        __syncthreads();
    }
}

// ---------------- launch ----------------
extern "C" void kernel_launch(void* const* d_in, const int* in_sizes, int n_in,
                              void* d_out, int out_size) {
    const float* latent  = (const float*)d_in[0];
    const int*   tokens  = (const int*)d_in[1];
    const float* W_emb   = (const float*)d_in[2];
    const float* b_emb   = (const float*)d_in[3];
    const float* W_init  = (const float*)d_in[4];
    const float* b_init  = (const float*)d_in[5];
    const float* Wih0    = (const float*)d_in[6];
    const float* Whh0    = (const float*)d_in[7];
    const float* bih0    = (const float*)d_in[8];
    const float* bhh0    = (const float*)d_in[9];
    const float* Wih1    = (const float*)d_in[10];
    const float* Whh1    = (const float*)d_in[11];
    const float* bih1    = (const float*)d_in[12];
    const float* bhh1    = (const float*)d_in[13];
    const float* Wih2    = (const float*)d_in[14];
    const float* Whh2    = (const float*)d_in[15];
    const float* bih2    = (const float*)d_in[16];
    const float* bhh2    = (const float*)d_in[17];
    const float* W_proj  = (const float*)d_in[18];
    const float* b_proj  = (const float*)d_in[19];

    float* out = (float*)d_out;
    size_t logits_elems = (size_t)Bsz * Ssz * Vsz;
    float* pred = ((size_t)out_size >= logits_elems + (size_t)Bsz * Ssz)
                      ? out + logits_elems : nullptr;

    k_prep<<<256, NTHR>>>(latent, W_emb, b_emb, W_init, b_init, Wih0, bih0, Whh0,
                          Wih1, Whh1, Wih2, Whh2, W_proj);
    k_main<<<NCTA, NTHR>>>(tokens, bhh0, bih1, bhh1, bih2, bhh2, b_proj, out, pred);
}

// round 14
// speedup vs baseline: 1.1436x; 1.1436x over previous
#include <cuda_runtime.h>
#include <math.h>

#define Bsz 1024
#define Ssz 350
#define Vsz 41
#define BT 8
#define NCTA 128
#define NTHR 256

typedef unsigned long long u64;

// ---------------- persistent device scratch ----------------
__device__ float4 g_wA[49152];     // Whh0: [kc][gate][256]
__device__ float4 g_wB1[24576];    // Wih1: [kc][gate][128]
__device__ float4 g_wB2[12288];    // Whh1: [kc][gate][128]
__device__ float4 g_wC1[3072];     // Wih2: [kc][gate][32]
__device__ float4 g_wC2[768];      // Whh2: [kc][gate][32]
__device__ float  g_WprojT[1312];  // [k][j]
__device__ float  g_G0[41 * 768];  // [v][col]
__device__ float  g_Hinit[Bsz * 416];

// ---------------- f32x2 helpers ----------------
__device__ __forceinline__ u64 fma2(u64 a, u64 b, u64 c) {
    u64 d; asm("fma.rn.f32x2 %0,%1,%2,%3;" : "=l"(d) : "l"(a), "l"(b), "l"(c)); return d;
}
__device__ __forceinline__ u64 pk2(float x, float y) {
    u64 d; asm("mov.b64 %0,{%1,%2};" : "=l"(d) : "f"(x), "f"(y)); return d;
}
__device__ __forceinline__ void up2(u64 a, float& x, float& y) {
    asm("mov.b64 {%0,%1}, %2;" : "=f"(x), "=f"(y) : "l"(a));
}
__device__ __forceinline__ float sigf(float x) {
    return __fdividef(1.0f, 1.0f + __expf(-x));
}
__device__ __forceinline__ float tanh_(float x) {
    float ax = fabsf(x);
    float e = __expf(-2.0f * ax);
    float t = __fdividef(1.0f - e, 1.0f + e);
    return copysignf(t, x);
}

// ---------------- fused prep kernel (identical to R12) ----------------
__global__ void k_prep(const float* __restrict__ latent, const float* __restrict__ W_emb,
                       const float* __restrict__ b_emb, const float* __restrict__ W_init,
                       const float* __restrict__ b_init, const float* __restrict__ Wih0,
                       const float* __restrict__ bih0, const float* __restrict__ Whh0,
                       const float* __restrict__ Wih1, const float* __restrict__ Whh1,
                       const float* __restrict__ Wih2, const float* __restrict__ Whh2,
                       const float* __restrict__ W_proj) {
    const int b = blockIdx.x, tid = threadIdx.x;
    if (b < 128) {
        __shared__ float lat[8 * 512];
        const int b0 = b * 8;
        for (int i = tid; i < 8 * 512; i += NTHR) lat[i] = latent[(size_t)b0 * 512 + i];
        __syncthreads();
        for (int c = tid; c < 416; c += NTHR) {
            float acc[8];
            float bi = b_init[c];
#pragma unroll
            for (int r = 0; r < 8; r++) acc[r] = bi;
            const float* w = W_init + (size_t)c * 512;
            for (int k = 0; k < 512; k += 4) {
                float4 wv = *(const float4*)(w + k);
#pragma unroll
                for (int r = 0; r < 8; r++) {
                    acc[r] += wv.x * lat[r * 512 + k];
                    acc[r] += wv.y * lat[r * 512 + k + 1];
                    acc[r] += wv.z * lat[r * 512 + k + 2];
                    acc[r] += wv.w * lat[r * 512 + k + 3];
                }
            }
#pragma unroll
            for (int r = 0; r < 8; r++) g_Hinit[(size_t)(b0 + r) * 416 + c] = acc[r];
        }
    } else if (b < 169) {
        const int v = b - 128;
        __shared__ float emb[512];
        for (int k = tid; k < 512; k += NTHR) emb[k] = W_emb[k * Vsz + v] + b_emb[k];
        __syncthreads();
        for (int j = tid; j < 768; j += NTHR) {
            float acc = bih0[j];
            const float* w = Wih0 + (size_t)j * 512;
            for (int k = 0; k < 512; k += 4) {
                float4 wv = *(const float4*)(w + k);
                acc += wv.x * emb[k] + wv.y * emb[k + 1] + wv.z * emb[k + 2] + wv.w * emb[k + 3];
            }
            g_G0[v * 768 + j] = acc;
        }
    } else {
        const int TOTAL = 90184;
        for (int i = (b - 169) * NTHR + tid; i < TOTAL; i += 87 * NTHR) {
            if (i < 49152) {
                int kc = i / 768, rem = i % 768;
                g_wA[i] = *(const float4*)&Whh0[(size_t)rem * 256 + 4 * kc];
            } else if (i < 73728) {
                int t = i - 49152;
                int kc = t / 384, row = t % 384;
                g_wB1[t] = *(const float4*)&Wih1[(size_t)row * 256 + 4 * kc];
            } else if (i < 86016) {
                int t = i - 73728;
                int kc = t / 384, row = t % 384;
                g_wB2[t] = *(const float4*)&Whh1[(size_t)row * 128 + 4 * kc];
            } else if (i < 89088) {
                int t = i - 86016;
                int kc = t / 96, row = t % 96;
                g_wC1[t] = *(const float4*)&Wih2[(size_t)row * 128 + 4 * kc];
            } else if (i < 89856) {
                int t = i - 89088;
                int kc = t / 96, row = t % 96;
                g_wC2[t] = *(const float4*)&Whh2[(size_t)row * 32 + 4 * kc];
            } else {
                int t2 = i - 89856;
#pragma unroll
                for (int c = 0; c < 4; c++) {
                    int e = t2 * 4 + c;
                    if (e < 1312) {
                        int k = e / Vsz, j = e - k * Vsz;
                        g_WprojT[e] = W_proj[j * 32 + k];
                    }
                }
            }
        }
    }
}

// ---------------- main persistent GRU kernel (R12 + 2-deep weight pipeline) ----------------
__global__ __launch_bounds__(NTHR, 1)
void k_main(const int* __restrict__ tokens,
            const float* __restrict__ bhh0,
            const float* __restrict__ bih1, const float* __restrict__ bhh1,
            const float* __restrict__ bih2, const float* __restrict__ bhh2,
            const float* __restrict__ b_proj,
            float* __restrict__ out, float* __restrict__ pred) {
    __shared__ __align__(16) u64 hrp0[256 * 4];
    __shared__ __align__(16) u64 hrp1[128 * 4];
    __shared__ __align__(16) u64 hrp2[32 * 4];
    __shared__ float lg[BT][44];
    __shared__ int toksAll[Ssz * 8];

    const int tid = threadIdx.x;
    const int b0 = blockIdx.x * BT;
    const int jj = tid & 127;
    const int rh = tid >> 7;
    const int rpb = 2 * rh;
    const int jc = tid & 31;
    const int qC = tid >> 5;

    for (int i = tid; i < Ssz * 8; i += NTHR) {
        int stt = i >> 3, row = i & 7;
        toksAll[i] = (stt == 0) ? 1 : tokens[(size_t)(b0 + row) * Ssz + stt];
    }
    for (int idx = tid; idx < BT * 416; idx += NTHR) {
        int row = idx / 416, c = idx - row * 416;
        float v = g_Hinit[(size_t)(b0 + row) * 416 + c];
        if (c < 256)      ((float*)hrp0)[c * 8 + row] = v;
        else if (c < 384) ((float*)hrp1)[(c - 256) * 8 + row] = v;
        else              ((float*)hrp2)[(c - 384) * 8 + row] = v;
    }

    const float bR0 = bhh0[tid], bZ0 = bhh0[256 + tid], bN0 = bhh0[512 + tid];
    const u64 bN0d = pk2(bN0, bN0);
    const u64 bBr = pk2(bih1[jj] + bhh1[jj], bih1[jj] + bhh1[jj]);
    const u64 bBz = pk2(bih1[128 + jj] + bhh1[128 + jj], bih1[128 + jj] + bhh1[128 + jj]);
    const u64 bBi = pk2(bih1[256 + jj], bih1[256 + jj]);
    const u64 bBh = pk2(bhh1[256 + jj], bhh1[256 + jj]);
    const u64 bCr = pk2(bih2[jc] + bhh2[jc], bih2[jc] + bhh2[jc]);
    const u64 bCz = pk2(bih2[32 + jc] + bhh2[32 + jc], bih2[32 + jc] + bhh2[32 + jc]);
    const u64 bCi = pk2(bih2[64 + jc], bih2[64 + jc]);
    const u64 bCh = pk2(bhh2[64 + jc], bhh2[64 + jc]);

    const float4* wAp = g_wA + tid;
    const float4* wB1p = g_wB1 + jj;
    const float4* wB2p = g_wB2 + jj;
    const float4* wC1p = g_wC1 + jc;
    const float4* wC2p = g_wC2 + jc;

    __syncthreads();

    for (int st = 0; st < Ssz; st++) {
        const int* tokrow = toksAll + st * 8;

        // ======== Phase A: col-owner, 8 rows, 2-deep pipelined weights ========
        {
            u64 aR[4], aZ[4], aN[4];
#pragma unroll
            for (int rp = 0; rp < 4; rp++) {
                const float* ge = g_G0 + (size_t)tokrow[2 * rp] * 768;
                const float* go = g_G0 + (size_t)tokrow[2 * rp + 1] * 768;
                aR[rp] = pk2(ge[tid] + bR0, go[tid] + bR0);
                aZ[rp] = pk2(ge[256 + tid] + bZ0, go[256 + tid] + bZ0);
                aN[rp] = bN0d;
            }
            float4 wr0 = wAp[0], wz0 = wAp[256], wn0 = wAp[512];
            float4 wr1 = wAp[768], wz1 = wAp[768 + 256], wn1 = wAp[768 + 512];
            for (int kc = 0; kc < 64; kc += 2) {
                int p2 = ((kc + 2) & 63) * 768, p3 = ((kc + 3) & 63) * 768;
                float4 nr0 = wAp[p2], nz0 = wAp[p2 + 256], nn0 = wAp[p2 + 512];
                float4 nr1 = wAp[p3], nz1 = wAp[p3 + 256], nn1 = wAp[p3 + 512];
#pragma unroll
                for (int half = 0; half < 2; half++) {
                    float4 wr = half ? wr1 : wr0;
                    float4 wz = half ? wz1 : wz0;
                    float4 wn = half ? wn1 : wn0;
                    const float wrr[4] = {wr.x, wr.y, wr.z, wr.w};
                    const float wzz[4] = {wz.x, wz.y, wz.z, wz.w};
                    const float wnn[4] = {wn.x, wn.y, wn.z, wn.w};
#pragma unroll
                    for (int c = 0; c < 4; c++) {
                        int k = 4 * (kc + half) + c;
                        ulonglong2 hA = *(const ulonglong2*)&hrp0[k * 4];
                        ulonglong2 hB = *(const ulonglong2*)&hrp0[k * 4 + 2];
                        u64 wrd = pk2(wrr[c], wrr[c]);
                        u64 wzd = pk2(wzz[c], wzz[c]);
                        u64 wnd = pk2(wnn[c], wnn[c]);
                        aR[0] = fma2(wrd, hA.x, aR[0]); aR[1] = fma2(wrd, hA.y, aR[1]);
                        aR[2] = fma2(wrd, hB.x, aR[2]); aR[3] = fma2(wrd, hB.y, aR[3]);
                        aZ[0] = fma2(wzd, hA.x, aZ[0]); aZ[1] = fma2(wzd, hA.y, aZ[1]);
                        aZ[2] = fma2(wzd, hB.x, aZ[2]); aZ[3] = fma2(wzd, hB.y, aZ[3]);
                        aN[0] = fma2(wnd, hA.x, aN[0]); aN[1] = fma2(wnd, hA.y, aN[1]);
                        aN[2] = fma2(wnd, hB.x, aN[2]); aN[3] = fma2(wnd, hB.y, aN[3]);
                    }
                }
                wr0 = nr0; wz0 = nz0; wn0 = nn0;
                wr1 = nr1; wz1 = nz1; wn1 = nn1;
            }
            __syncthreads();
#pragma unroll
            for (int rp = 0; rp < 4; rp++) {
                float r0e, r1e, z0e, z1e, n0e, n1e, h0e, h1e;
                up2(aR[rp], r0e, r1e); up2(aZ[rp], z0e, z1e); up2(aN[rp], n0e, n1e);
                float gi0 = g_G0[(size_t)tokrow[2 * rp] * 768 + 512 + tid];
                float gi1 = g_G0[(size_t)tokrow[2 * rp + 1] * 768 + 512 + tid];
                up2(hrp0[tid * 4 + rp], h0e, h1e);
                float rg0 = sigf(r0e), rg1 = sigf(r1e);
                float zg0 = sigf(z0e), zg1 = sigf(z1e);
                float ng0 = tanh_(gi0 + rg0 * n0e), ng1 = tanh_(gi1 + rg1 * n1e);
                float v0 = (1.0f - zg0) * ng0 + zg0 * h0e;
                float v1 = (1.0f - zg1) * ng1 + zg1 * h1e;
                hrp0[tid * 4 + rp] = pk2(v0, v1);
            }
            __syncthreads();
        }

        // ======== Phase B: (jj, rh), 4 rows, 2-deep pipelined ========
        {
            u64 rB[2], zB[2], iB[2], hB[2];
#pragma unroll
            for (int i = 0; i < 2; i++) { rB[i] = bBr; zB[i] = bBz; iB[i] = bBi; hB[i] = bBh; }
            {
                float4 wr0 = wB1p[0], wz0 = wB1p[128], wn0 = wB1p[256];
                float4 wr1 = wB1p[384], wz1 = wB1p[384 + 128], wn1 = wB1p[384 + 256];
                for (int kc = 0; kc < 64; kc += 2) {
                    int p2 = ((kc + 2) & 63) * 384, p3 = ((kc + 3) & 63) * 384;
                    float4 nr0 = wB1p[p2], nz0 = wB1p[p2 + 128], nn0 = wB1p[p2 + 256];
                    float4 nr1 = wB1p[p3], nz1 = wB1p[p3 + 128], nn1 = wB1p[p3 + 256];
#pragma unroll
                    for (int half = 0; half < 2; half++) {
                        float4 wr = half ? wr1 : wr0;
                        float4 wz = half ? wz1 : wz0;
                        float4 wn = half ? wn1 : wn0;
                        const float wrr[4] = {wr.x, wr.y, wr.z, wr.w};
                        const float wzz[4] = {wz.x, wz.y, wz.z, wz.w};
                        const float wnn[4] = {wn.x, wn.y, wn.z, wn.w};
#pragma unroll
                        for (int c = 0; c < 4; c++) {
                            int k = 4 * (kc + half) + c;
                            ulonglong2 h = *(const ulonglong2*)&hrp0[k * 4 + rpb];
                            u64 wrd = pk2(wrr[c], wrr[c]);
                            u64 wzd = pk2(wzz[c], wzz[c]);
                            u64 wnd = pk2(wnn[c], wnn[c]);
                            rB[0] = fma2(wrd, h.x, rB[0]); rB[1] = fma2(wrd, h.y, rB[1]);
                            zB[0] = fma2(wzd, h.x, zB[0]); zB[1] = fma2(wzd, h.y, zB[1]);
                            iB[0] = fma2(wnd, h.x, iB[0]); iB[1] = fma2(wnd, h.y, iB[1]);
                        }
                    }
                    wr0 = nr0; wz0 = nz0; wn0 = nn0;
                    wr1 = nr1; wz1 = nz1; wn1 = nn1;
                }
            }
            {
                float4 wr0 = wB2p[0], wz0 = wB2p[128], wn0 = wB2p[256];
                float4 wr1 = wB2p[384], wz1 = wB2p[384 + 128], wn1 = wB2p[384 + 256];
                for (int kc = 0; kc < 32; kc += 2) {
                    int p2 = ((kc + 2) & 31) * 384, p3 = ((kc + 3) & 31) * 384;
                    float4 nr0 = wB2p[p2], nz0 = wB2p[p2 + 128], nn0 = wB2p[p2 + 256];
                    float4 nr1 = wB2p[p3], nz1 = wB2p[p3 + 128], nn1 = wB2p[p3 + 256];
#pragma unroll
                    for (int half = 0; half < 2; half++) {
                        float4 wr = half ? wr1 : wr0;
                        float4 wz = half ? wz1 : wz0;
                        float4 wn = half ? wn1 : wn0;
                        const float wrr[4] = {wr.x, wr.y, wr.z, wr.w};
                        const float wzz[4] = {wz.x, wz.y, wz.z, wz.w};
                        const float wnn[4] = {wn.x, wn.y, wn.z, wn.w};
#pragma unroll
                        for (int c = 0; c < 4; c++) {
                            int k = 4 * (kc + half) + c;
                            ulonglong2 h = *(const ulonglong2*)&hrp1[k * 4 + rpb];
                            u64 wrd = pk2(wrr[c], wrr[c]);
                            u64 wzd = pk2(wzz[c], wzz[c]);
                            u64 wnd = pk2(wnn[c], wnn[c]);
                            rB[0] = fma2(wrd, h.x, rB[0]); rB[1] = fma2(wrd, h.y, rB[1]);
                            zB[0] = fma2(wzd, h.x, zB[0]); zB[1] = fma2(wzd, h.y, zB[1]);
                            hB[0] = fma2(wnd, h.x, hB[0]); hB[1] = fma2(wnd, h.y, hB[1]);
                        }
                    }
                    wr0 = nr0; wz0 = nz0; wn0 = nn0;
                    wr1 = nr1; wz1 = nz1; wn1 = nn1;
                }
            }
            __syncthreads();
#pragma unroll
            for (int i = 0; i < 2; i++) {
                float r0e, r1e, z0e, z1e, i0e, i1e, n0e, n1e, h0e, h1e;
                up2(rB[i], r0e, r1e); up2(zB[i], z0e, z1e);
                up2(iB[i], i0e, i1e); up2(hB[i], n0e, n1e);
                up2(hrp1[jj * 4 + rpb + i], h0e, h1e);
                float rg0 = sigf(r0e), rg1 = sigf(r1e);
                float zg0 = sigf(z0e), zg1 = sigf(z1e);
                float ng0 = tanh_(i0e + rg0 * n0e), ng1 = tanh_(i1e + rg1 * n1e);
                float v0 = (1.0f - zg0) * ng0 + zg0 * h0e;
                float v1 = (1.0f - zg1) * ng1 + zg1 * h1e;
                hrp1[jj * 4 + rpb + i] = pk2(v0, v1);
            }
            __syncthreads();
        }

        // ======== Phase C (direct, 128 threads) ========
        if (tid < 128) {
            u64 rC = bCr, zC = bCz, iC = bCi, hC = bCh;
            for (int kc = 0; kc < 32; kc++) {
                float4 wr = wC1p[kc * 96];
                float4 wz = wC1p[kc * 96 + 32];
                float4 wn = wC1p[kc * 96 + 64];
                const float wrr[4] = {wr.x, wr.y, wr.z, wr.w};
                const float wzz[4] = {wz.x, wz.y, wz.z, wz.w};
                const float wnn[4] = {wn.x, wn.y, wn.z, wn.w};
#pragma unroll
                for (int c = 0; c < 4; c++) {
                    u64 h = hrp1[(4 * kc + c) * 4 + qC];
                    rC = fma2(pk2(wrr[c], wrr[c]), h, rC);
                    zC = fma2(pk2(wzz[c], wzz[c]), h, zC);
                    iC = fma2(pk2(wnn[c], wnn[c]), h, iC);
                }
            }
            for (int kc = 0; kc < 8; kc++) {
                float4 wr = wC2p[kc * 96];
                float4 wz = wC2p[kc * 96 + 32];
                float4 wn = wC2p[kc * 96 + 64];
                const float wrr[4] = {wr.x, wr.y, wr.z, wr.w};
                const float wzz[4] = {wz.x, wz.y, wz.z, wz.w};
                const float wnn[4] = {wn.x, wn.y, wn.z, wn.w};
#pragma unroll
                for (int c = 0; c < 4; c++) {
                    u64 h = hrp2[(4 * kc + c) * 4 + qC];
                    rC = fma2(pk2(wrr[c], wrr[c]), h, rC);
                    zC = fma2(pk2(wzz[c], wzz[c]), h, zC);
                    hC = fma2(pk2(wnn[c], wnn[c]), h, hC);
                }
            }
            __syncthreads();
            {
                float r0e, r1e, z0e, z1e, i0e, i1e, n0e, n1e, h0e, h1e;
                up2(rC, r0e, r1e); up2(zC, z0e, z1e);
                up2(iC, i0e, i1e); up2(hC, n0e, n1e);
                up2(hrp2[jc * 4 + qC], h0e, h1e);
                float rg0 = sigf(r0e), rg1 = sigf(r1e);
                float zg0 = sigf(z0e), zg1 = sigf(z1e);
                float ng0 = tanh_(i0e + rg0 * n0e), ng1 = tanh_(i1e + rg1 * n1e);
                float v0 = (1.0f - zg0) * ng0 + zg0 * h0e;
                float v1 = (1.0f - zg1) * ng1 + zg1 * h1e;
                hrp2[jc * 4 + qC] = pk2(v0, v1);
            }
        } else {
            __syncthreads();
        }
        __syncthreads();

        // ======== Phase D: projection + argmax ========
        {
            const float* h2f = (const float*)hrp2;
            for (int idx = tid; idx < BT * Vsz; idx += NTHR) {
                int row = idx / Vsz, j = idx - row * Vsz;
                float acc = b_proj[j];
#pragma unroll
                for (int k = 0; k < 32; k++)
                    acc += g_WprojT[k * Vsz + j] * h2f[k * 8 + row];
                out[((size_t)(b0 + row) * Ssz + st) * Vsz + j] = acc;
                lg[row][j] = acc;
            }
        }
        __syncthreads();
        if (tid < BT && pred) {
            float best = lg[tid][0];
            int bi = 0;
#pragma unroll 1
            for (int j = 1; j < Vsz; j++) {
                float v = lg[tid][j];
                if (v > best) { best = v; bi = j; }
            }
            pred[(size_t)(b0 + tid) * Ssz + st] = (float)bi;
        }
        __syncthreads();
    }
}

// ---------------- launch ----------------
extern "C" void kernel_launch(void* const* d_in, const int* in_sizes, int n_in,
                              void* d_out, int out_size) {
    const float* latent  = (const float*)d_in[0];
    const int*   tokens  = (const int*)d_in[1];
    const float* W_emb   = (const float*)d_in[2];
    const float* b_emb   = (const float*)d_in[3];
    const float* W_init  = (const float*)d_in[4];
    const float* b_init  = (const float*)d_in[5];
    const float* Wih0    = (const float*)d_in[6];
    const float* Whh0    = (const float*)d_in[7];
    const float* bih0    = (const float*)d_in[8];
    const float* bhh0    = (const float*)d_in[9];
    const float* Wih1    = (const float*)d_in[10];
    const float* Whh1    = (const float*)d_in[11];
    const float* bih1    = (const float*)d_in[12];
    const float* bhh1    = (const float*)d_in[13];
    const float* Wih2    = (const float*)d_in[14];
    const float* Whh2    = (const float*)d_in[15];
    const float* bih2    = (const float*)d_in[16];
    const float* bhh2    = (const float*)d_in[17];
    const float* W_proj  = (const float*)d_in[18];
    const float* b_proj  = (const float*)d_in[19];

    float* out = (float*)d_out;
    size_t logits_elems = (size_t)Bsz * Ssz * Vsz;
    float* pred = ((size_t)out_size >= logits_elems + (size_t)Bsz * Ssz)
                      ? out + logits_elems : nullptr;

    k_prep<<<256, NTHR>>>(latent, W_emb, b_emb, W_init, b_init, Wih0, bih0, Whh0,
                          Wih1, Whh1, Wih2, Whh2, W_proj);
    k_main<<<NCTA, NTHR>>>(tokens, bhh0, bih1, bhh1, bih2, bhh2, b_proj, out, pred);
}